// round 13
// baseline (speedup 1.0000x reference)
#include <cuda_runtime.h>
#include <cuda_bf16.h>
#include <math.h>
#include <stdint.h>

// Problem constants
#define BATCH 2
#define SEQ   2048
#define DMODEL 1024
#define NHEAD 16
#define HDIM  64
#define MTOT  (BATCH*SEQ)   // 4096
#define NBH   (BATCH*NHEAD) // 32

typedef unsigned short u16;

// ---- scratch (device globals) ----
__device__ u16 g_xh[MTOT*DMODEL],     g_xl[MTOT*DMODEL];
__device__ u16 g_wh[3*DMODEL*DMODEL], g_wl[3*DMODEL*DMODEL];
__device__ u16 g_woh[DMODEL*DMODEL],  g_wol[DMODEL*DMODEL];
__device__ u16 g_qh[NBH*SEQ*HDIM],  g_ql[NBH*SEQ*HDIM];
__device__ u16 g_kh[NBH*SEQ*HDIM],  g_kl[NBH*SEQ*HDIM];
__device__ u16 g_vth[NBH*HDIM*SEQ], g_vtl[NBH*HDIM*SEQ]; // [bh][d][s]
__device__ u16 g_cth[MTOT*DMODEL],  g_ctl[MTOT*DMODEL];  // split ctx

// ----------------------------------------------------------------------------
// helpers
// ----------------------------------------------------------------------------
__device__ __forceinline__ uint32_t pack_split(float x, float y, uint32_t& lo_pack)
{
    uint32_t h;
    asm("cvt.rn.bf16x2.f32 %0, %1, %2;" : "=r"(h) : "f"(y), "f"(x));
    float hx = __uint_as_float(h << 16);
    float hy = __uint_as_float(h & 0xffff0000u);
    asm("cvt.rn.bf16x2.f32 %0, %1, %2;" : "=r"(lo_pack) : "f"(y - hy), "f"(x - hx));
    return h;
}

__device__ __forceinline__ uint32_t smem_u32(const void* p)
{
    return (uint32_t)__cvta_generic_to_shared(p);
}

#define MMA_BF16(d, a, b)                                                   \
    asm volatile("mma.sync.aligned.m16n8k16.row.col.f32.bf16.bf16.f32 "     \
                 "{%0,%1,%2,%3}, {%4,%5,%6,%7}, {%8,%9}, {%0,%1,%2,%3};"    \
                 : "+f"((d)[0]), "+f"((d)[1]), "+f"((d)[2]), "+f"((d)[3])   \
                 : "r"((a)[0]), "r"((a)[1]), "r"((a)[2]), "r"((a)[3]),      \
                   "r"((b)[0]), "r"((b)[1]))

#define LDSM_X4(r0, r1, r2, r3, addr)                                        \
    asm volatile("ldmatrix.sync.aligned.m8n8.x4.shared.b16 {%0,%1,%2,%3}, [%4];" \
                 : "=r"(r0), "=r"(r1), "=r"(r2), "=r"(r3) : "r"(addr))

#define CP16(dst, src)                                                       \
    asm volatile("cp.async.ca.shared.global [%0], [%1], 16;"                 \
                 :: "r"(dst), "l"(src) : "memory")

// ----------------------------------------------------------------------------
// split pass: fp32 -> bf16 hi/lo
// ----------------------------------------------------------------------------
__global__ __launch_bounds__(256) void split_fp32(const float* __restrict__ src,
                                                  int which, int n4)
{
    int i = blockIdx.x*blockDim.x + threadIdx.x;
    if (i >= n4) return;
    float4 v = ((const float4*)src)[i];
    uint32_t l01, l23;
    uint32_t h01 = pack_split(v.x, v.y, l01);
    uint32_t h23 = pack_split(v.z, v.w, l23);
    u16* dh = (which == 0) ? g_xh : (which == 1) ? g_wh : g_woh;
    u16* dl = (which == 0) ? g_xl : (which == 1) ? g_wl : g_wol;
    ((uint2*)dh)[i] = make_uint2(h01, h23);
    ((uint2*)dl)[i] = make_uint2(l01, l23);
}

// ----------------------------------------------------------------------------
// bf16x3 GEMM, warp tile 64x64, block 128x128, 128 threads (2Mx2N warps).
// Pre-split inputs; cp.async double-buffered KC=32 chunks; LDSM fragments.
// EPI 0: A=x, B=Wqkv -> scatter split q/k/v.  EPI 1: A=ctx, B=Wout -> out+bias.
// Dynamic smem: 2 buffers x 4 arrays x 128 rows x 20 u32 (80B stride).
// ----------------------------------------------------------------------------
#define ROWU 20                 // u32 per smem row (16 data + 4 pad)
#define ARR  (128*ROWU*4)       // 10240 B per array
#define BUFSZ (4*ARR)           // 40960 B per buffer
#define GSMEM (2*BUFSZ)         // 81920 B

template <int EPI>
__global__ __launch_bounds__(128, 2) void hgemm_128(const float* __restrict__ bias,
                                                    float* __restrict__ C)
{
    extern __shared__ __align__(16) char dsm[];

    const int tid   = threadIdx.x;
    const int lane  = tid & 31;
    const int warp  = tid >> 5;
    const int g     = lane >> 2;
    const int q     = lane & 3;
    const int warpM = warp >> 1;        // 0..1
    const int warpN = warp & 1;         // 0..1
    const int m0 = blockIdx.x * 128;
    const int n0 = blockIdx.y * 128;

    // ldmatrix lane addressing (proven R11 patterns)
    const int a_row = lane & 15;
    const int a_chk = (lane >> 4) << 2;
    const int b_rof = ((lane >> 4) << 3) + (lane & 7);
    const int b_chk = ((lane >> 3) & 1) << 2;

    // gmem row pointers: thread t owns A row t and B row t of the tile
    const long aoff = (long)(m0 + tid) * DMODEL;
    const long boff = (long)(n0 + tid) * DMODEL;
    const u16* pAh = (EPI == 0) ? (g_xh + aoff) : (g_cth + aoff);
    const u16* pAl = (EPI == 0) ? (g_xl + aoff) : (g_ctl + aoff);
    const u16* pBh = (EPI == 0) ? (g_wh + boff) : (g_woh + boff);
    const u16* pBl = (EPI == 0) ? (g_wl + boff) : (g_wol + boff);

    const uint32_t sbase = smem_u32(dsm);
    const uint32_t rowb  = (uint32_t)tid * (ROWU*4);   // byte offset of this thread's row

    // issue one chunk's cp.asyncs (chunk c -> buffer c&1)
    auto issue = [&](int c) {
        uint32_t b = sbase + (uint32_t)(c & 1) * BUFSZ + rowb;
        const u16* sA_h = pAh + c*32;
        const u16* sA_l = pAl + c*32;
        const u16* sB_h = pBh + c*32;
        const u16* sB_l = pBl + c*32;
        #pragma unroll
        for (int j = 0; j < 4; j++) {
            CP16(b + 0*ARR + j*16, sA_h + j*8);
            CP16(b + 1*ARR + j*16, sA_l + j*8);
            CP16(b + 2*ARR + j*16, sB_h + j*8);
            CP16(b + 3*ARR + j*16, sB_l + j*8);
        }
        asm volatile("cp.async.commit_group;" ::: "memory");
    };

    float acc[4][8][4] = {};

    issue(0);
    issue(1);

    for (int c = 0; c < 32; c++) {
        if (c <= 29) asm volatile("cp.async.wait_group 1;" ::: "memory");
        else         asm volatile("cp.async.wait_group 0;" ::: "memory");
        __syncthreads();

        char* buf = dsm + (c & 1) * BUFSZ;
        uint32_t (*Ah)[ROWU] = (uint32_t(*)[ROWU])(buf);
        uint32_t (*Al)[ROWU] = (uint32_t(*)[ROWU])(buf + ARR);
        uint32_t (*Bh)[ROWU] = (uint32_t(*)[ROWU])(buf + 2*ARR);
        uint32_t (*Bl)[ROWU] = (uint32_t(*)[ROWU])(buf + 3*ARR);

        #pragma unroll
        for (int ks = 0; ks < 2; ks++) {
            const int kc = ks*8;
            uint32_t afh[4][4], afl[4][4];
            #pragma unroll
            for (int mi = 0; mi < 4; mi++) {
                const int r = warpM*64 + mi*16;
                LDSM_X4(afh[mi][0], afh[mi][1], afh[mi][2], afh[mi][3],
                        smem_u32(&Ah[r + a_row][kc + a_chk]));
                LDSM_X4(afl[mi][0], afl[mi][1], afl[mi][2], afl[mi][3],
                        smem_u32(&Al[r + a_row][kc + a_chk]));
            }
            #pragma unroll
            for (int p = 0; p < 4; p++) {
                const int nb = warpN*64 + p*16;
                uint32_t bh0[2], bh1[2], bl0[2], bl1[2];
                LDSM_X4(bh0[0], bh0[1], bh1[0], bh1[1],
                        smem_u32(&Bh[nb + b_rof][kc + b_chk]));
                LDSM_X4(bl0[0], bl0[1], bl1[0], bl1[1],
                        smem_u32(&Bl[nb + b_rof][kc + b_chk]));
                #pragma unroll
                for (int mi = 0; mi < 4; mi++) {
                    MMA_BF16(acc[mi][2*p],   afh[mi], bh0);
                    MMA_BF16(acc[mi][2*p],   afh[mi], bl0);
                    MMA_BF16(acc[mi][2*p],   afl[mi], bh0);
                    MMA_BF16(acc[mi][2*p+1], afh[mi], bh1);
                    MMA_BF16(acc[mi][2*p+1], afh[mi], bl1);
                    MMA_BF16(acc[mi][2*p+1], afl[mi], bh1);
                }
            }
        }
        __syncthreads();
        if (c + 2 < 32) issue(c + 2);
    }

    // ---------------- epilogue ----------------
    if (EPI == 0) {
        const int t = n0 >> 10;   // 0=q 1=k 2=v (128-tile never spans types)
        #pragma unroll
        for (int mi = 0; mi < 4; mi++) {
            #pragma unroll
            for (int half = 0; half < 2; half++) {
                int m  = m0 + warpM*64 + mi*16 + g + half*8;
                int bb = m >> 11;
                int ss = m & 2047;
                #pragma unroll
                for (int ni = 0; ni < 8; ni++) {
                    int n = n0 + warpN*64 + ni*8 + 2*q;
                    int head = (n & 1023) >> 6;
                    int hc = n & 63;
                    int bh = bb*NHEAD + head;
                    float v0 = half ? acc[mi][ni][2] : acc[mi][ni][0];
                    float v1 = half ? acc[mi][ni][3] : acc[mi][ni][1];
                    uint32_t lo;
                    uint32_t hi = pack_split(v0, v1, lo);
                    if (t == 0) {
                        long idx = ((long)bh*SEQ + ss)*HDIM + hc;
                        *(uint32_t*)&g_qh[idx] = hi;
                        *(uint32_t*)&g_ql[idx] = lo;
                    } else if (t == 1) {
                        long idx = ((long)bh*SEQ + ss)*HDIM + hc;
                        *(uint32_t*)&g_kh[idx] = hi;
                        *(uint32_t*)&g_kl[idx] = lo;
                    } else {
                        long base = (long)bh*HDIM*SEQ;
                        g_vth[base + (long)hc*SEQ + ss]     = (u16)(hi & 0xffffu);
                        g_vth[base + (long)(hc+1)*SEQ + ss] = (u16)(hi >> 16);
                        g_vtl[base + (long)hc*SEQ + ss]     = (u16)(lo & 0xffffu);
                        g_vtl[base + (long)(hc+1)*SEQ + ss] = (u16)(lo >> 16);
                    }
                }
            }
        }
    } else {
        #pragma unroll
        for (int mi = 0; mi < 4; mi++) {
            #pragma unroll
            for (int half = 0; half < 2; half++) {
                int m = m0 + warpM*64 + mi*16 + g + half*8;
                float* crow = C + (long)m*DMODEL;
                #pragma unroll
                for (int ni = 0; ni < 8; ni++) {
                    int n = n0 + warpN*64 + ni*8 + 2*q;
                    float2 bv = *(const float2*)(bias + n);
                    float2 o = half ? make_float2(acc[mi][ni][2] + bv.x, acc[mi][ni][3] + bv.y)
                                    : make_float2(acc[mi][ni][0] + bv.x, acc[mi][ni][1] + bv.y);
                    *(float2*)(crow + n) = o;
                }
            }
        }
    }
}

// ----------------------------------------------------------------------------
// MMA flash attention (bf16x3), LDSM fragment loads — R11-proven core.
// Epilogue writes split ctx for the tensor-core out-projection.
// ----------------------------------------------------------------------------
__global__ __launch_bounds__(256, 1) void attn_mma()
{
    __shared__ __align__(16) uint32_t Kh[64][36], Kl[64][36], Vh[64][36], Vl[64][36];

    const int tid  = threadIdx.x;
    const int lane = tid & 31;
    const int warp = tid >> 5;
    const int g = lane >> 2;
    const int q = lane & 3;
    const int qt = blockIdx.x;          // 0..15
    const int bh = blockIdx.y;          // 0..31
    const int row0 = qt*128 + warp*16;

    const int b_rof = ((lane >> 4) << 3) + (lane & 7);
    const int b_chk = ((lane >> 3) & 1) << 2;

    uint32_t qfh[4][4], qfl[4][4];
    {
        const uint32_t* q0h = (const uint32_t*)&g_qh[((long)bh*SEQ + row0)*HDIM];
        const uint32_t* q0l = (const uint32_t*)&g_ql[((long)bh*SEQ + row0)*HDIM];
        #pragma unroll
        for (int ks = 0; ks < 4; ks++) {
            qfh[ks][0] = q0h[g*32 + ks*8 + q];
            qfh[ks][1] = q0h[(g+8)*32 + ks*8 + q];
            qfh[ks][2] = q0h[g*32 + ks*8 + q + 4];
            qfh[ks][3] = q0h[(g+8)*32 + ks*8 + q + 4];
            qfl[ks][0] = q0l[g*32 + ks*8 + q];
            qfl[ks][1] = q0l[(g+8)*32 + ks*8 + q];
            qfl[ks][2] = q0l[g*32 + ks*8 + q + 4];
            qfl[ks][3] = q0l[(g+8)*32 + ks*8 + q + 4];
        }
    }

    float oacc[8][4] = {};
    float mrow0 = -1e30f, mrow1 = -1e30f;
    float lrow0 = 0.f,    lrow1 = 0.f;

    const int ld_r = tid >> 2;
    const int ld_c = (tid & 3) * 8;
    const int u4i  = (tid & 3) * 2;

    const int ktmax = 2*qt + 1;
    for (int kt = 0; kt <= ktmax; kt++) {
        __syncthreads();
        {
            long koff = ((long)bh*SEQ + kt*64 + ld_r)*HDIM;
            const uint4* kh4 = (const uint4*)&g_kh[koff];
            const uint4* kl4 = (const uint4*)&g_kl[koff];
            long voff = ((long)bh*HDIM + ld_r)*SEQ + kt*64;
            const uint4* vh4 = (const uint4*)&g_vth[voff];
            const uint4* vl4 = (const uint4*)&g_vtl[voff];
            *(uint4*)&Kh[ld_r][ld_c]   = kh4[u4i];
            *(uint4*)&Kh[ld_r][ld_c+4] = kh4[u4i+1];
            *(uint4*)&Kl[ld_r][ld_c]   = kl4[u4i];
            *(uint4*)&Kl[ld_r][ld_c+4] = kl4[u4i+1];
            *(uint4*)&Vh[ld_r][ld_c]   = vh4[u4i];
            *(uint4*)&Vh[ld_r][ld_c+4] = vh4[u4i+1];
            *(uint4*)&Vl[ld_r][ld_c]   = vl4[u4i];
            *(uint4*)&Vl[ld_r][ld_c+4] = vl4[u4i+1];
        }
        __syncthreads();

        if (row0 + 15 < kt*64) continue;

        float s[8][4] = {};
        #pragma unroll
        for (int ks = 0; ks < 4; ks++) {
            const int kc = ks*8;
            #pragma unroll
            for (int p = 0; p < 4; p++) {
                const int nb = p*16;
                uint32_t bh0[2], bh1[2], bl0[2], bl1[2];
                LDSM_X4(bh0[0], bh0[1], bh1[0], bh1[1],
                        smem_u32(&Kh[nb + b_rof][kc + b_chk]));
                LDSM_X4(bl0[0], bl0[1], bl1[0], bl1[1],
                        smem_u32(&Kl[nb + b_rof][kc + b_chk]));
                MMA_BF16(s[2*p],   qfh[ks], bh0);
                MMA_BF16(s[2*p],   qfh[ks], bl0);
                MMA_BF16(s[2*p],   qfl[ks], bh0);
                MMA_BF16(s[2*p+1], qfh[ks], bh1);
                MMA_BF16(s[2*p+1], qfh[ks], bl1);
                MMA_BF16(s[2*p+1], qfl[ks], bh1);
            }
        }

        if (kt*64 + 63 > row0) {
            #pragma unroll
            for (int nt = 0; nt < 8; nt++) {
                int c0 = kt*64 + nt*8 + 2*q;
                int r0r = row0 + g;
                int r1r = row0 + g + 8;
                if (c0     > r0r) s[nt][0] = -1e30f;
                if (c0 + 1 > r0r) s[nt][1] = -1e30f;
                if (c0     > r1r) s[nt][2] = -1e30f;
                if (c0 + 1 > r1r) s[nt][3] = -1e30f;
            }
        }

        float mx0 = -1e30f, mx1 = -1e30f;
        #pragma unroll
        for (int nt = 0; nt < 8; nt++) {
            mx0 = fmaxf(mx0, fmaxf(s[nt][0], s[nt][1]));
            mx1 = fmaxf(mx1, fmaxf(s[nt][2], s[nt][3]));
        }
        mx0 = fmaxf(mx0, __shfl_xor_sync(0xffffffffu, mx0, 1));
        mx0 = fmaxf(mx0, __shfl_xor_sync(0xffffffffu, mx0, 2));
        mx1 = fmaxf(mx1, __shfl_xor_sync(0xffffffffu, mx1, 1));
        mx1 = fmaxf(mx1, __shfl_xor_sync(0xffffffffu, mx1, 2));

        float mn0 = fmaxf(mrow0, mx0);
        float mn1 = fmaxf(mrow1, mx1);
        float sc0 = __expf(mrow0 - mn0);
        float sc1 = __expf(mrow1 - mn1);
        mrow0 = mn0; mrow1 = mn1;

        float sum0 = 0.f, sum1 = 0.f;
        #pragma unroll
        for (int nt = 0; nt < 8; nt++) {
            s[nt][0] = __expf(s[nt][0] - mn0);
            s[nt][1] = __expf(s[nt][1] - mn0);
            s[nt][2] = __expf(s[nt][2] - mn1);
            s[nt][3] = __expf(s[nt][3] - mn1);
            sum0 += s[nt][0] + s[nt][1];
            sum1 += s[nt][2] + s[nt][3];
        }
        sum0 += __shfl_xor_sync(0xffffffffu, sum0, 1);
        sum0 += __shfl_xor_sync(0xffffffffu, sum0, 2);
        sum1 += __shfl_xor_sync(0xffffffffu, sum1, 1);
        sum1 += __shfl_xor_sync(0xffffffffu, sum1, 2);
        lrow0 = lrow0*sc0 + sum0;
        lrow1 = lrow1*sc1 + sum1;

        #pragma unroll
        for (int dt = 0; dt < 8; dt++) {
            oacc[dt][0] *= sc0; oacc[dt][1] *= sc0;
            oacc[dt][2] *= sc1; oacc[dt][3] *= sc1;
        }

        uint32_t ph[8][2], pl[8][2];
        #pragma unroll
        for (int nt = 0; nt < 8; nt++) {
            ph[nt][0] = pack_split(s[nt][0], s[nt][1], pl[nt][0]);
            ph[nt][1] = pack_split(s[nt][2], s[nt][3], pl[nt][1]);
        }

        #pragma unroll
        for (int ks2 = 0; ks2 < 4; ks2++) {
            const int kc = ks2*8;
            uint32_t afh[4] = { ph[2*ks2][0], ph[2*ks2][1], ph[2*ks2+1][0], ph[2*ks2+1][1] };
            uint32_t afl[4] = { pl[2*ks2][0], pl[2*ks2][1], pl[2*ks2+1][0], pl[2*ks2+1][1] };
            #pragma unroll
            for (int p = 0; p < 4; p++) {
                const int nb = p*16;
                uint32_t bh0[2], bh1[2], bl0[2], bl1[2];
                LDSM_X4(bh0[0], bh0[1], bh1[0], bh1[1],
                        smem_u32(&Vh[nb + b_rof][kc + b_chk]));
                LDSM_X4(bl0[0], bl0[1], bl1[0], bl1[1],
                        smem_u32(&Vl[nb + b_rof][kc + b_chk]));
                MMA_BF16(oacc[2*p],   afh, bh0);
                MMA_BF16(oacc[2*p],   afh, bl0);
                MMA_BF16(oacc[2*p],   afl, bh0);
                MMA_BF16(oacc[2*p+1], afh, bh1);
                MMA_BF16(oacc[2*p+1], afh, bl1);
                MMA_BF16(oacc[2*p+1], afl, bh1);
            }
        }
    }

    // ---- epilogue: normalize + write SPLIT ctx [b*s][h*64+d] ----
    const float i0 = 1.f / lrow0;
    const float i1 = 1.f / lrow1;
    const int bb   = bh >> 4;
    const int head = bh & 15;
    #pragma unroll
    for (int dt = 0; dt < 8; dt++) {
        int col = head*64 + dt*8 + q*2;
        long r0 = (long)bb*SEQ + row0 + g;
        long r1 = r0 + 8;
        uint32_t lo0, lo1;
        uint32_t hi0 = pack_split(oacc[dt][0]*i0, oacc[dt][1]*i0, lo0);
        uint32_t hi1 = pack_split(oacc[dt][2]*i1, oacc[dt][3]*i1, lo1);
        *(uint32_t*)&g_cth[r0*DMODEL + col] = hi0;
        *(uint32_t*)&g_ctl[r0*DMODEL + col] = lo0;
        *(uint32_t*)&g_cth[r1*DMODEL + col] = hi1;
        *(uint32_t*)&g_ctl[r1*DMODEL + col] = lo1;
    }
}

// ----------------------------------------------------------------------------
extern "C" void kernel_launch(void* const* d_in, const int* in_sizes, int n_in,
                              void* d_out, int out_size)
{
    const float* x    = (const float*)d_in[0];   // [2,2048,1024]
    const float* Wqkv = (const float*)d_in[1];   // [3072,1024]
    const float* Wout = (const float*)d_in[2];   // [1024,1024]
    const float* bout = (const float*)d_in[3];   // [1024]
    float* out = (float*)d_out;                  // [2,2048,1024]

    cudaFuncSetAttribute(hgemm_128<0>, cudaFuncAttributeMaxDynamicSharedMemorySize, GSMEM);
    cudaFuncSetAttribute(hgemm_128<1>, cudaFuncAttributeMaxDynamicSharedMemorySize, GSMEM);

    split_fp32<<<(MTOT*DMODEL/4 + 255)/256, 256>>>(x, 0, MTOT*DMODEL/4);
    split_fp32<<<(3*DMODEL*DMODEL/4 + 255)/256, 256>>>(Wqkv, 1, 3*DMODEL*DMODEL/4);
    split_fp32<<<(DMODEL*DMODEL/4 + 255)/256, 256>>>(Wout, 2, DMODEL*DMODEL/4);

    hgemm_128<0><<<dim3(MTOT/128, 3*DMODEL/128), 128, GSMEM>>>(nullptr, nullptr);
    attn_mma<<<dim3(SEQ/128, NBH), 256>>>();
    hgemm_128<1><<<dim3(MTOT/128, DMODEL/128), 128, GSMEM>>>(bout, out);
}

// round 15
// speedup vs baseline: 1.2257x; 1.2257x over previous
#include <cuda_runtime.h>
#include <cuda_bf16.h>
#include <math.h>
#include <stdint.h>

// Problem constants
#define BATCH 2
#define SEQ   2048
#define DMODEL 1024
#define NHEAD 16
#define HDIM  64
#define MTOT  (BATCH*SEQ)   // 4096
#define NBH   (BATCH*NHEAD) // 32

typedef unsigned short u16;

// ---- scratch (device globals) ----
__device__ u16 g_xh[MTOT*DMODEL],     g_xl[MTOT*DMODEL];
__device__ u16 g_wh[3*DMODEL*DMODEL], g_wl[3*DMODEL*DMODEL];
__device__ u16 g_woh[DMODEL*DMODEL],  g_wol[DMODEL*DMODEL];
__device__ u16 g_qh[NBH*SEQ*HDIM],  g_ql[NBH*SEQ*HDIM];
__device__ u16 g_kh[NBH*SEQ*HDIM],  g_kl[NBH*SEQ*HDIM];
__device__ u16 g_vth[NBH*HDIM*SEQ], g_vtl[NBH*HDIM*SEQ]; // [bh][d][s]
__device__ u16 g_cth[MTOT*DMODEL],  g_ctl[MTOT*DMODEL];  // split ctx

// ----------------------------------------------------------------------------
// helpers
// ----------------------------------------------------------------------------
__device__ __forceinline__ uint32_t pack_split(float x, float y, uint32_t& lo_pack)
{
    uint32_t h;
    asm("cvt.rn.bf16x2.f32 %0, %1, %2;" : "=r"(h) : "f"(y), "f"(x));
    float hx = __uint_as_float(h << 16);
    float hy = __uint_as_float(h & 0xffff0000u);
    asm("cvt.rn.bf16x2.f32 %0, %1, %2;" : "=r"(lo_pack) : "f"(y - hy), "f"(x - hx));
    return h;
}

__device__ __forceinline__ uint32_t smem_u32(const void* p)
{
    return (uint32_t)__cvta_generic_to_shared(p);
}

#define MMA_BF16(d, a, b)                                                   \
    asm volatile("mma.sync.aligned.m16n8k16.row.col.f32.bf16.bf16.f32 "     \
                 "{%0,%1,%2,%3}, {%4,%5,%6,%7}, {%8,%9}, {%0,%1,%2,%3};"    \
                 : "+f"((d)[0]), "+f"((d)[1]), "+f"((d)[2]), "+f"((d)[3])   \
                 : "r"((a)[0]), "r"((a)[1]), "r"((a)[2]), "r"((a)[3]),      \
                   "r"((b)[0]), "r"((b)[1]))

#define LDSM_X4(r0, r1, r2, r3, addr)                                        \
    asm volatile("ldmatrix.sync.aligned.m8n8.x4.shared.b16 {%0,%1,%2,%3}, [%4];" \
                 : "=r"(r0), "=r"(r1), "=r"(r2), "=r"(r3) : "r"(addr))

#define CP16(dst, src)                                                       \
    asm volatile("cp.async.ca.shared.global [%0], [%1], 16;"                 \
                 :: "r"(dst), "l"(src) : "memory")

// ----------------------------------------------------------------------------
// split pass: fp32 -> bf16 hi/lo
// ----------------------------------------------------------------------------
__global__ __launch_bounds__(256) void split_fp32(const float* __restrict__ src,
                                                  int which, int n4)
{
    int i = blockIdx.x*blockDim.x + threadIdx.x;
    if (i >= n4) return;
    float4 v = ((const float4*)src)[i];
    uint32_t l01, l23;
    uint32_t h01 = pack_split(v.x, v.y, l01);
    uint32_t h23 = pack_split(v.z, v.w, l23);
    u16* dh = (which == 0) ? g_xh : (which == 1) ? g_wh : g_woh;
    u16* dl = (which == 0) ? g_xl : (which == 1) ? g_wl : g_wol;
    ((uint2*)dh)[i] = make_uint2(h01, h23);
    ((uint2*)dl)[i] = make_uint2(l01, l23);
}

// ----------------------------------------------------------------------------
// bf16x3 GEMM: block 128x128, 256 threads = 8 warps (2M x 4N), warp tile 64x32.
// Pre-split inputs; cp.async double-buffered KC=32 chunks; LDSM fragments.
// EPI 0: A=x, B=Wqkv -> scatter split q/k/v.  EPI 1: A=ctx, B=Wout -> out+bias.
// ----------------------------------------------------------------------------
#define ROWU 20                 // u32 per smem row (16 data + 4 pad)
#define ARR  (128*ROWU*4)       // 10240 B per array
#define BUFSZ (4*ARR)           // 40960 B per buffer
#define GSMEM (2*BUFSZ)         // 81920 B

template <int EPI>
__global__ __launch_bounds__(256, 2) void hgemm_128(const float* __restrict__ bias,
                                                    float* __restrict__ C)
{
    extern __shared__ __align__(16) char dsm[];

    const int tid   = threadIdx.x;
    const int lane  = tid & 31;
    const int warp  = tid >> 5;
    const int g     = lane >> 2;
    const int q     = lane & 3;
    const int warpM = warp >> 2;        // 0..1 (64 rows each)
    const int warpN = warp & 3;         // 0..3 (32 cols each)
    const int m0 = blockIdx.x * 128;
    const int n0 = blockIdx.y * 128;

    // ldmatrix lane addressing (proven R11 patterns)
    const int a_row = lane & 15;
    const int a_chk = (lane >> 4) << 2;
    const int b_rof = ((lane >> 4) << 3) + (lane & 7);
    const int b_chk = ((lane >> 3) & 1) << 2;

    // loader mapping: 256 threads, row = tid>>1, half = tid&1 (2x16B per array)
    const int lrow  = tid >> 1;
    const int lhalf = tid & 1;
    const long aoff = (long)(m0 + lrow) * DMODEL + lhalf*16;
    const long boff = (long)(n0 + lrow) * DMODEL + lhalf*16;
    const u16* pAh = (EPI == 0) ? (g_xh + aoff) : (g_cth + aoff);
    const u16* pAl = (EPI == 0) ? (g_xl + aoff) : (g_ctl + aoff);
    const u16* pBh = (EPI == 0) ? (g_wh + boff) : (g_woh + boff);
    const u16* pBl = (EPI == 0) ? (g_wl + boff) : (g_wol + boff);

    const uint32_t sbase = smem_u32(dsm);
    const uint32_t rowb  = (uint32_t)lrow * (ROWU*4) + (uint32_t)lhalf*32;

    auto issue = [&](int c) {
        uint32_t b = sbase + (uint32_t)(c & 1) * BUFSZ + rowb;
        const u16* sA_h = pAh + c*32;
        const u16* sA_l = pAl + c*32;
        const u16* sB_h = pBh + c*32;
        const u16* sB_l = pBl + c*32;
        #pragma unroll
        for (int j = 0; j < 2; j++) {
            CP16(b + 0*ARR + j*16, sA_h + j*8);
            CP16(b + 1*ARR + j*16, sA_l + j*8);
            CP16(b + 2*ARR + j*16, sB_h + j*8);
            CP16(b + 3*ARR + j*16, sB_l + j*8);
        }
        asm volatile("cp.async.commit_group;" ::: "memory");
    };

    float acc[4][4][4] = {};

    issue(0);
    issue(1);

    for (int c = 0; c < 32; c++) {
        if (c <= 29) asm volatile("cp.async.wait_group 1;" ::: "memory");
        else         asm volatile("cp.async.wait_group 0;" ::: "memory");
        __syncthreads();

        char* buf = dsm + (c & 1) * BUFSZ;
        uint32_t (*Ah)[ROWU] = (uint32_t(*)[ROWU])(buf);
        uint32_t (*Al)[ROWU] = (uint32_t(*)[ROWU])(buf + ARR);
        uint32_t (*Bh)[ROWU] = (uint32_t(*)[ROWU])(buf + 2*ARR);
        uint32_t (*Bl)[ROWU] = (uint32_t(*)[ROWU])(buf + 3*ARR);

        #pragma unroll
        for (int ks = 0; ks < 2; ks++) {
            const int kc = ks*8;
            uint32_t afh[4][4], afl[4][4];
            #pragma unroll
            for (int mi = 0; mi < 4; mi++) {
                const int r = warpM*64 + mi*16;
                LDSM_X4(afh[mi][0], afh[mi][1], afh[mi][2], afh[mi][3],
                        smem_u32(&Ah[r + a_row][kc + a_chk]));
                LDSM_X4(afl[mi][0], afl[mi][1], afl[mi][2], afl[mi][3],
                        smem_u32(&Al[r + a_row][kc + a_chk]));
            }
            #pragma unroll
            for (int p = 0; p < 2; p++) {
                const int nb = warpN*32 + p*16;
                uint32_t bh0[2], bh1[2], bl0[2], bl1[2];
                LDSM_X4(bh0[0], bh0[1], bh1[0], bh1[1],
                        smem_u32(&Bh[nb + b_rof][kc + b_chk]));
                LDSM_X4(bl0[0], bl0[1], bl1[0], bl1[1],
                        smem_u32(&Bl[nb + b_rof][kc + b_chk]));
                #pragma unroll
                for (int mi = 0; mi < 4; mi++) {
                    MMA_BF16(acc[mi][2*p],   afh[mi], bh0);
                    MMA_BF16(acc[mi][2*p],   afh[mi], bl0);
                    MMA_BF16(acc[mi][2*p],   afl[mi], bh0);
                    MMA_BF16(acc[mi][2*p+1], afh[mi], bh1);
                    MMA_BF16(acc[mi][2*p+1], afh[mi], bl1);
                    MMA_BF16(acc[mi][2*p+1], afl[mi], bh1);
                }
            }
        }
        __syncthreads();
        if (c + 2 < 32) issue(c + 2);
    }

    // ---------------- epilogue ----------------
    if (EPI == 0) {
        const int t = n0 >> 10;   // 0=q 1=k 2=v (128-tile never spans types)
        #pragma unroll
        for (int mi = 0; mi < 4; mi++) {
            #pragma unroll
            for (int half = 0; half < 2; half++) {
                int m  = m0 + warpM*64 + mi*16 + g + half*8;
                int bb = m >> 11;
                int ss = m & 2047;
                #pragma unroll
                for (int ni = 0; ni < 4; ni++) {
                    int n = n0 + warpN*32 + ni*8 + 2*q;
                    int head = (n & 1023) >> 6;
                    int hc = n & 63;
                    int bh = bb*NHEAD + head;
                    float v0 = half ? acc[mi][ni][2] : acc[mi][ni][0];
                    float v1 = half ? acc[mi][ni][3] : acc[mi][ni][1];
                    uint32_t lo;
                    uint32_t hi = pack_split(v0, v1, lo);
                    if (t == 0) {
                        long idx = ((long)bh*SEQ + ss)*HDIM + hc;
                        *(uint32_t*)&g_qh[idx] = hi;
                        *(uint32_t*)&g_ql[idx] = lo;
                    } else if (t == 1) {
                        long idx = ((long)bh*SEQ + ss)*HDIM + hc;
                        *(uint32_t*)&g_kh[idx] = hi;
                        *(uint32_t*)&g_kl[idx] = lo;
                    } else {
                        long base = (long)bh*HDIM*SEQ;
                        g_vth[base + (long)hc*SEQ + ss]     = (u16)(hi & 0xffffu);
                        g_vth[base + (long)(hc+1)*SEQ + ss] = (u16)(hi >> 16);
                        g_vtl[base + (long)hc*SEQ + ss]     = (u16)(lo & 0xffffu);
                        g_vtl[base + (long)(hc+1)*SEQ + ss] = (u16)(lo >> 16);
                    }
                }
            }
        }
    } else {
        #pragma unroll
        for (int mi = 0; mi < 4; mi++) {
            #pragma unroll
            for (int half = 0; half < 2; half++) {
                int m = m0 + warpM*64 + mi*16 + g + half*8;
                float* crow = C + (long)m*DMODEL;
                #pragma unroll
                for (int ni = 0; ni < 4; ni++) {
                    int n = n0 + warpN*32 + ni*8 + 2*q;
                    float2 bv = *(const float2*)(bias + n);
                    float2 o = half ? make_float2(acc[mi][ni][2] + bv.x, acc[mi][ni][3] + bv.y)
                                    : make_float2(acc[mi][ni][0] + bv.x, acc[mi][ni][1] + bv.y);
                    *(float2*)(crow + n) = o;
                }
            }
        }
    }
}

// ----------------------------------------------------------------------------
// MMA flash attention (bf16x3), LDSM fragment loads — R11-proven core.
// Epilogue writes split ctx for the tensor-core out-projection.
// ----------------------------------------------------------------------------
__global__ __launch_bounds__(256, 1) void attn_mma()
{
    __shared__ __align__(16) uint32_t Kh[64][36], Kl[64][36], Vh[64][36], Vl[64][36];

    const int tid  = threadIdx.x;
    const int lane = tid & 31;
    const int warp = tid >> 5;
    const int g = lane >> 2;
    const int q = lane & 3;
    const int qt = blockIdx.x;          // 0..15
    const int bh = blockIdx.y;          // 0..31
    const int row0 = qt*128 + warp*16;

    const int b_rof = ((lane >> 4) << 3) + (lane & 7);
    const int b_chk = ((lane >> 3) & 1) << 2;

    uint32_t qfh[4][4], qfl[4][4];
    {
        const uint32_t* q0h = (const uint32_t*)&g_qh[((long)bh*SEQ + row0)*HDIM];
        const uint32_t* q0l = (const uint32_t*)&g_ql[((long)bh*SEQ + row0)*HDIM];
        #pragma unroll
        for (int ks = 0; ks < 4; ks++) {
            qfh[ks][0] = q0h[g*32 + ks*8 + q];
            qfh[ks][1] = q0h[(g+8)*32 + ks*8 + q];
            qfh[ks][2] = q0h[g*32 + ks*8 + q + 4];
            qfh[ks][3] = q0h[(g+8)*32 + ks*8 + q + 4];
            qfl[ks][0] = q0l[g*32 + ks*8 + q];
            qfl[ks][1] = q0l[(g+8)*32 + ks*8 + q];
            qfl[ks][2] = q0l[g*32 + ks*8 + q + 4];
            qfl[ks][3] = q0l[(g+8)*32 + ks*8 + q + 4];
        }
    }

    float oacc[8][4] = {};
    float mrow0 = -1e30f, mrow1 = -1e30f;
    float lrow0 = 0.f,    lrow1 = 0.f;

    const int ld_r = tid >> 2;
    const int ld_c = (tid & 3) * 8;
    const int u4i  = (tid & 3) * 2;

    const int ktmax = 2*qt + 1;
    for (int kt = 0; kt <= ktmax; kt++) {
        __syncthreads();
        {
            long koff = ((long)bh*SEQ + kt*64 + ld_r)*HDIM;
            const uint4* kh4 = (const uint4*)&g_kh[koff];
            const uint4* kl4 = (const uint4*)&g_kl[koff];
            long voff = ((long)bh*HDIM + ld_r)*SEQ + kt*64;
            const uint4* vh4 = (const uint4*)&g_vth[voff];
            const uint4* vl4 = (const uint4*)&g_vtl[voff];
            *(uint4*)&Kh[ld_r][ld_c]   = kh4[u4i];
            *(uint4*)&Kh[ld_r][ld_c+4] = kh4[u4i+1];
            *(uint4*)&Kl[ld_r][ld_c]   = kl4[u4i];
            *(uint4*)&Kl[ld_r][ld_c+4] = kl4[u4i+1];
            *(uint4*)&Vh[ld_r][ld_c]   = vh4[u4i];
            *(uint4*)&Vh[ld_r][ld_c+4] = vh4[u4i+1];
            *(uint4*)&Vl[ld_r][ld_c]   = vl4[u4i];
            *(uint4*)&Vl[ld_r][ld_c+4] = vl4[u4i+1];
        }
        __syncthreads();

        if (row0 + 15 < kt*64) continue;

        float s[8][4] = {};
        #pragma unroll
        for (int ks = 0; ks < 4; ks++) {
            const int kc = ks*8;
            #pragma unroll
            for (int p = 0; p < 4; p++) {
                const int nb = p*16;
                uint32_t bh0[2], bh1[2], bl0[2], bl1[2];
                LDSM_X4(bh0[0], bh0[1], bh1[0], bh1[1],
                        smem_u32(&Kh[nb + b_rof][kc + b_chk]));
                LDSM_X4(bl0[0], bl0[1], bl1[0], bl1[1],
                        smem_u32(&Kl[nb + b_rof][kc + b_chk]));
                MMA_BF16(s[2*p],   qfh[ks], bh0);
                MMA_BF16(s[2*p],   qfh[ks], bl0);
                MMA_BF16(s[2*p],   qfl[ks], bh0);
                MMA_BF16(s[2*p+1], qfh[ks], bh1);
                MMA_BF16(s[2*p+1], qfh[ks], bl1);
                MMA_BF16(s[2*p+1], qfl[ks], bh1);
            }
        }

        if (kt*64 + 63 > row0) {
            #pragma unroll
            for (int nt = 0; nt < 8; nt++) {
                int c0 = kt*64 + nt*8 + 2*q;
                int r0r = row0 + g;
                int r1r = row0 + g + 8;
                if (c0     > r0r) s[nt][0] = -1e30f;
                if (c0 + 1 > r0r) s[nt][1] = -1e30f;
                if (c0     > r1r) s[nt][2] = -1e30f;
                if (c0 + 1 > r1r) s[nt][3] = -1e30f;
            }
        }

        float mx0 = -1e30f, mx1 = -1e30f;
        #pragma unroll
        for (int nt = 0; nt < 8; nt++) {
            mx0 = fmaxf(mx0, fmaxf(s[nt][0], s[nt][1]));
            mx1 = fmaxf(mx1, fmaxf(s[nt][2], s[nt][3]));
        }
        mx0 = fmaxf(mx0, __shfl_xor_sync(0xffffffffu, mx0, 1));
        mx0 = fmaxf(mx0, __shfl_xor_sync(0xffffffffu, mx0, 2));
        mx1 = fmaxf(mx1, __shfl_xor_sync(0xffffffffu, mx1, 1));
        mx1 = fmaxf(mx1, __shfl_xor_sync(0xffffffffu, mx1, 2));

        float mn0 = fmaxf(mrow0, mx0);
        float mn1 = fmaxf(mrow1, mx1);
        float sc0 = __expf(mrow0 - mn0);
        float sc1 = __expf(mrow1 - mn1);
        mrow0 = mn0; mrow1 = mn1;

        float sum0 = 0.f, sum1 = 0.f;
        #pragma unroll
        for (int nt = 0; nt < 8; nt++) {
            s[nt][0] = __expf(s[nt][0] - mn0);
            s[nt][1] = __expf(s[nt][1] - mn0);
            s[nt][2] = __expf(s[nt][2] - mn1);
            s[nt][3] = __expf(s[nt][3] - mn1);
            sum0 += s[nt][0] + s[nt][1];
            sum1 += s[nt][2] + s[nt][3];
        }
        sum0 += __shfl_xor_sync(0xffffffffu, sum0, 1);
        sum0 += __shfl_xor_sync(0xffffffffu, sum0, 2);
        sum1 += __shfl_xor_sync(0xffffffffu, sum1, 1);
        sum1 += __shfl_xor_sync(0xffffffffu, sum1, 2);
        lrow0 = lrow0*sc0 + sum0;
        lrow1 = lrow1*sc1 + sum1;

        #pragma unroll
        for (int dt = 0; dt < 8; dt++) {
            oacc[dt][0] *= sc0; oacc[dt][1] *= sc0;
            oacc[dt][2] *= sc1; oacc[dt][3] *= sc1;
        }

        uint32_t ph[8][2], pl[8][2];
        #pragma unroll
        for (int nt = 0; nt < 8; nt++) {
            ph[nt][0] = pack_split(s[nt][0], s[nt][1], pl[nt][0]);
            ph[nt][1] = pack_split(s[nt][2], s[nt][3], pl[nt][1]);
        }

        #pragma unroll
        for (int ks2 = 0; ks2 < 4; ks2++) {
            const int kc = ks2*8;
            uint32_t afh[4] = { ph[2*ks2][0], ph[2*ks2][1], ph[2*ks2+1][0], ph[2*ks2+1][1] };
            uint32_t afl[4] = { pl[2*ks2][0], pl[2*ks2][1], pl[2*ks2+1][0], pl[2*ks2+1][1] };
            #pragma unroll
            for (int p = 0; p < 4; p++) {
                const int nb = p*16;
                uint32_t bh0[2], bh1[2], bl0[2], bl1[2];
                LDSM_X4(bh0[0], bh0[1], bh1[0], bh1[1],
                        smem_u32(&Vh[nb + b_rof][kc + b_chk]));
                LDSM_X4(bl0[0], bl0[1], bl1[0], bl1[1],
                        smem_u32(&Vl[nb + b_rof][kc + b_chk]));
                MMA_BF16(oacc[2*p],   afh, bh0);
                MMA_BF16(oacc[2*p],   afh, bl0);
                MMA_BF16(oacc[2*p],   afl, bh0);
                MMA_BF16(oacc[2*p+1], afh, bh1);
                MMA_BF16(oacc[2*p+1], afh, bl1);
                MMA_BF16(oacc[2*p+1], afl, bh1);
            }
        }
    }

    // ---- epilogue: normalize + write SPLIT ctx [b*s][h*64+d] ----
    const float i0 = 1.f / lrow0;
    const float i1 = 1.f / lrow1;
    const int bb   = bh >> 4;
    const int head = bh & 15;
    #pragma unroll
    for (int dt = 0; dt < 8; dt++) {
        int col = head*64 + dt*8 + q*2;
        long r0 = (long)bb*SEQ + row0 + g;
        long r1 = r0 + 8;
        uint32_t lo0, lo1;
        uint32_t hi0 = pack_split(oacc[dt][0]*i0, oacc[dt][1]*i0, lo0);
        uint32_t hi1 = pack_split(oacc[dt][2]*i1, oacc[dt][3]*i1, lo1);
        *(uint32_t*)&g_cth[r0*DMODEL + col] = hi0;
        *(uint32_t*)&g_ctl[r0*DMODEL + col] = lo0;
        *(uint32_t*)&g_cth[r1*DMODEL + col] = hi1;
        *(uint32_t*)&g_ctl[r1*DMODEL + col] = lo1;
    }
}

// ----------------------------------------------------------------------------
extern "C" void kernel_launch(void* const* d_in, const int* in_sizes, int n_in,
                              void* d_out, int out_size)
{
    const float* x    = (const float*)d_in[0];   // [2,2048,1024]
    const float* Wqkv = (const float*)d_in[1];   // [3072,1024]
    const float* Wout = (const float*)d_in[2];   // [1024,1024]
    const float* bout = (const float*)d_in[3];   // [1024]
    float* out = (float*)d_out;                  // [2,2048,1024]

    cudaFuncSetAttribute(hgemm_128<0>, cudaFuncAttributeMaxDynamicSharedMemorySize, GSMEM);
    cudaFuncSetAttribute(hgemm_128<1>, cudaFuncAttributeMaxDynamicSharedMemorySize, GSMEM);

    split_fp32<<<(MTOT*DMODEL/4 + 255)/256, 256>>>(x, 0, MTOT*DMODEL/4);
    split_fp32<<<(3*DMODEL*DMODEL/4 + 255)/256, 256>>>(Wqkv, 1, 3*DMODEL*DMODEL/4);
    split_fp32<<<(DMODEL*DMODEL/4 + 255)/256, 256>>>(Wout, 2, DMODEL*DMODEL/4);

    hgemm_128<0><<<dim3(MTOT/128, 3*DMODEL/128), 256, GSMEM>>>(nullptr, nullptr);
    attn_mma<<<dim3(SEQ/128, NBH), 256>>>();
    hgemm_128<1><<<dim3(MTOT/128, DMODEL/128), 256, GSMEM>>>(bout, out);
}